// round 16
// baseline (speedup 1.0000x reference)
#include <cuda_runtime.h>
#include <cuda_fp16.h>
#include <cstdint>

// out[B=256, N] = (inputs @ features^T) / 0.07
// R15: R14 with __stcs reverted to plain stores (single-variable isolation).
// Persistent CTAs, A resident 160KB smem, warp 64x32, tile M=256 x N=128,
// KC=32 F double-buffer, one sync/iter. Tail: the (ntiles % grid) remainder
// tiles are each handled by TWO CTAs (one per M-half; inactive warps still
// stage F + sync), halving per-SMSP load during the tail wave.

#define KC 32
#define NCH 8
#define NT 128
#define ROWB 80u                 // 64B k-row + 16B pad
#define ACHUNK 20480u            // 256 rows * 80B per k-chunk
#define ARES   (8u * ACHUNK)     // 163840
#define OFF_F  ARES
#define FSTAGE 10240u            // 128 * 80
#define SMEM_TOTAL (163840 + 2 * 10240)   // 184320
#define SCALE (1.0f / 0.07f)

__device__ __align__(16) __half g_A16[256 * 256];

// ---------------- helpers ----------------
__device__ __forceinline__ uint32_t smem_u32(const void* p) {
    uint32_t r;
    asm("{ .reg .u64 t; cvta.to.shared.u64 t, %1; cvt.u32.u64 %0, t; }" : "=r"(r) : "l"(p));
    return r;
}
__device__ __forceinline__ uint32_t pack_f16x2(float hi, float lo) {
    uint32_t r;
    asm("cvt.rn.f16x2.f32 %0, %1, %2;" : "=r"(r) : "f"(hi), "f"(lo));
    return r;
}
__device__ __forceinline__ void sts128(uint32_t a, uint32_t x, uint32_t y, uint32_t z, uint32_t w) {
    asm volatile("st.shared.v4.b32 [%0], {%1,%2,%3,%4};"
                 :: "r"(a), "r"(x), "r"(y), "r"(z), "r"(w) : "memory");
}
__device__ __forceinline__ void ldm4(uint32_t* r, uint32_t a) {
    asm volatile("ldmatrix.sync.aligned.m8n8.x4.shared.b16 {%0,%1,%2,%3}, [%4];"
                 : "=r"(r[0]), "=r"(r[1]), "=r"(r[2]), "=r"(r[3]) : "r"(a));
}
__device__ __forceinline__ void mma16816(float* d, const uint32_t* a, const uint32_t* b) {
    asm volatile("mma.sync.aligned.m16n8k16.row.col.f32.f16.f16.f32 "
                 "{%0,%1,%2,%3}, {%4,%5,%6,%7}, {%8,%9}, {%0,%1,%2,%3};"
                 : "+f"(d[0]), "+f"(d[1]), "+f"(d[2]), "+f"(d[3])
                 : "r"(a[0]), "r"(a[1]), "r"(a[2]), "r"(a[3]), "r"(b[0]), "r"(b[1]));
}
__device__ __forceinline__ void cp_async16(uint32_t dst, const void* src) {
    asm volatile("cp.async.cg.shared.global [%0], [%1], 16;" :: "r"(dst), "l"(src) : "memory");
}
#define CP_COMMIT asm volatile("cp.async.commit_group;" ::: "memory")
#define CP_WAIT0  asm volatile("cp.async.wait_group 0;" ::: "memory")

// ---------------- A convert kernel ----------------
__global__ void sct_cvtA(const float* __restrict__ A) {
    int i = blockIdx.x * 256 + threadIdx.x;   // 65536 elems
    g_A16[i] = __float2half_rn(A[i]);
}

// ---------------- main GEMM (persistent + split tail) ----------------
__global__ __launch_bounds__(512, 1)
void sct_mma_kernel(const float* __restrict__ F, float* __restrict__ C,
                    int N, int ntiles)
{
    extern __shared__ char smem[];
    const uint32_t sb = smem_u32(smem);          // A resident: 8 chunks
    const uint32_t fb = sb + OFF_F;              // F stages (2)
    const int tid  = threadIdx.x;
    const int lane = tid & 31;
    const int wid  = tid >> 5;

    // ---- A residency load: once per CTA ----
    {
        const int ar = tid >> 1;                 // row 0..255
        const int ah = tid & 1;                  // 32B half
        const uint32_t dst0 = (uint32_t)ar * ROWB + (uint32_t)ah * 32u;
        const __half* src0 = g_A16 + ar * 256 + ah * 16;
        #pragma unroll
        for (int c = 0; c < NCH; c++) {
            const uint32_t dst = sb + (uint32_t)c * ACHUNK + dst0;
            const __half* src = src0 + c * KC;
            cp_async16(dst,      src);
            cp_async16(dst + 16, src + 8);
        }
        CP_COMMIT;
    }

    // F staging: row = tid>>2 (0..127), q = tid&3 -> 8 floats (32B)
    const int frow = tid >> 2;
    const int fq   = tid & 3;
    const uint32_t f_sts = (uint32_t)frow * ROWB + (uint32_t)fq * 16u;

    // warp tiling: 4 m-warps x 4 n-warps, warp tile 64x32
    const int wm = wid & 3;
    const int wn = wid >> 2;
    const int mbase = wm * 64;
    const int nb    = wn * 32;

    const uint32_t afrag = (uint32_t)(mbase + (lane & 15)) * ROWB + (uint32_t)((lane >> 4) * 16);
    const uint32_t bfrag = (uint32_t)(nb + (lane & 7) + ((lane >> 4) << 3)) * ROWB
                         + (uint32_t)(((lane >> 3) & 1) << 4);

    float4 pf0, pf1;
    const float* fsrc;
    auto fptr = [&](int tile) -> const float* {
        int fn = tile * NT + frow;
        if (fn > N - 1) fn = N - 1;              // clamp; stores guarded
        return F + (size_t)fn * 256 + fq * 8;
    };
    auto ldgF = [&](int c) {
        const float4* p = (const float4*)(fsrc + c * KC);
        pf0 = p[0]; pf1 = p[1];
    };
    auto stsF = [&](int c) {
        sts128(fb + (uint32_t)(c & 1) * FSTAGE + f_sts,
               pack_f16x2(pf0.y, pf0.x), pack_f16x2(pf0.w, pf0.z),
               pack_f16x2(pf1.y, pf1.x), pack_f16x2(pf1.w, pf1.z));
    };

    // run one tile; mactive gates compute + stores (inactive warps still
    // stage F and hit the barriers). next_tile >= 0 -> prefetch its chunk 0.
    auto run_tile = [&](int tile, bool mactive, int next_tile) {
        const int n0 = tile * NT;
        float acc[4][4][4];
        #pragma unroll
        for (int i = 0; i < 4; i++)
            #pragma unroll
            for (int j = 0; j < 4; j++)
                #pragma unroll
                for (int q = 0; q < 4; q++) acc[i][j][q] = 0.0f;

        stsF(0);
        __syncthreads();

        #pragma unroll
        for (int c = 0; c < NCH; c++) {
            if (c + 1 < NCH) ldgF(c + 1);
            if (mactive) {
                const uint32_t ast = sb + (uint32_t)c * ACHUNK;
                const uint32_t fst = fb + (uint32_t)(c & 1) * FSTAGE;
                #pragma unroll
                for (int ks = 0; ks < 2; ks++) {
                    const uint32_t ko = ks * 32;
                    uint32_t b0[4], b1[4], a[4][4];
                    ldm4(b0, fst + bfrag + ko);                 // n-tiles 0,1
                    ldm4(b1, fst + bfrag + 16 * ROWB + ko);     // n-tiles 2,3
                    #pragma unroll
                    for (int i = 0; i < 4; i++)
                        ldm4(a[i], ast + afrag + (uint32_t)i * (16 * ROWB) + ko);
                    #pragma unroll
                    for (int i = 0; i < 4; i++) {
                        mma16816(acc[i][0], a[i], b0 + 0);
                        mma16816(acc[i][1], a[i], b0 + 2);
                        mma16816(acc[i][2], a[i], b1 + 0);
                        mma16816(acc[i][3], a[i], b1 + 2);
                    }
                }
            }
            if (c + 1 < NCH) {
                stsF(c + 1);
                __syncthreads();
            }
        }

        if (next_tile >= 0) {               // prefetch hidden by epilogue
            fsrc = fptr(next_tile);
            ldgF(0);
        }

        if (mactive) {
            #pragma unroll
            for (int i = 0; i < 4; i++) {
                const int m = mbase + i * 16 + (lane >> 2);
                #pragma unroll
                for (int j = 0; j < 4; j++) {
                    const int n = n0 + nb + j * 8 + (lane & 3) * 2;
                    if (n < N) {   // N even, n even -> n+1 also valid
                        float* p0 = C + (size_t)m * N + n;
                        float* p1 = C + (size_t)(m + 8) * N + n;
                        *(float2*)p0 = make_float2(acc[i][j][0] * SCALE, acc[i][j][1] * SCALE);
                        *(float2*)p1 = make_float2(acc[i][j][2] * SCALE, acc[i][j][3] * SCALE);
                    }
                }
            }
        }
    };

    // wait for A once
    CP_WAIT0;

    const int stride = gridDim.x;
    const int full   = ntiles / stride;
    const int rem    = ntiles - full * stride;
    const bool split = (2 * rem <= stride);

    // my tail assignment
    int tail = -1, mhalf = 0;
    if (rem > 0) {
        if (split) {
            if ((int)blockIdx.x < 2 * rem) {
                tail  = full * stride + ((int)blockIdx.x >> 1);
                mhalf = blockIdx.x & 1;
            }
        } else if ((int)blockIdx.x < rem) {
            tail = full * stride + blockIdx.x;
        }
    }

    if (full > 0) {
        fsrc = fptr(blockIdx.x);
        ldgF(0);
        #pragma unroll 1
        for (int r = 0; r < full; r++) {
            const int tile = blockIdx.x + r * stride;
            const int next = (r + 1 < full) ? tile + stride : tail;
            run_tile(tile, true, next);
        }
    }
    if (tail >= 0) {
        if (full == 0) { fsrc = fptr(tail); ldgF(0); }
        const bool act = split ? ((wm >> 1) == mhalf) : true;
        run_tile(tail, act, -1);
    }
}

// ---------------- launch ----------------
extern "C" void kernel_launch(void* const* d_in, const int* in_sizes, int n_in,
                              void* d_out, int out_size)
{
    const float* inputs   = (const float*)d_in[0];  // [256, 256]
    const float* features = (const float*)d_in[2];  // [N, 256]
    const int D = 256;
    const int N = in_sizes[2] / D;

    sct_cvtA<<<256, 256>>>(inputs);

    int nsm = 148;
    cudaDeviceGetAttribute(&nsm, cudaDevAttrMultiProcessorCount, 0);

    const int ntiles = (N + NT - 1) / NT;
    int grid = nsm < ntiles ? nsm : ntiles;

    cudaFuncSetAttribute(sct_mma_kernel, cudaFuncAttributeMaxDynamicSharedMemorySize, SMEM_TOTAL);
    sct_mma_kernel<<<grid, 512, SMEM_TOTAL>>>(features, (float*)d_out, N, ntiles);
}

// round 17
// speedup vs baseline: 1.0066x; 1.0066x over previous
#include <cuda_runtime.h>
#include <cuda_fp16.h>
#include <cstdint>

// out[B=256, N] = (inputs @ features^T) / 0.07
// R16: R12's hot loop verbatim (persistent CTAs, A resident 160KB smem,
// warp 64x32, tile M=256 x N=128, KC=32 F double-buffer, one sync/iter,
// branch-free mainloop) + tail-split in a SEPARATE duplicated code path:
// the (ntiles % grid) remainder tiles are each handled by two CTAs (one per
// M-half, gated per-warp; inactive warps still stage F + sync). The full-
// round path carries zero extra branches (R14/R15 showed merging the gate
// into the hot loop costs ~3us on every tile).

#define KC 32
#define NCH 8
#define NT 128
#define ROWB 80u                 // 64B k-row + 16B pad
#define ACHUNK 20480u            // 256 rows * 80B per k-chunk
#define ARES   (8u * ACHUNK)     // 163840
#define OFF_F  ARES
#define FSTAGE 10240u            // 128 * 80
#define SMEM_TOTAL (163840 + 2 * 10240)   // 184320
#define SCALE (1.0f / 0.07f)

__device__ __align__(16) __half g_A16[256 * 256];

// ---------------- helpers ----------------
__device__ __forceinline__ uint32_t smem_u32(const void* p) {
    uint32_t r;
    asm("{ .reg .u64 t; cvta.to.shared.u64 t, %1; cvt.u32.u64 %0, t; }" : "=r"(r) : "l"(p));
    return r;
}
__device__ __forceinline__ uint32_t pack_f16x2(float hi, float lo) {
    uint32_t r;
    asm("cvt.rn.f16x2.f32 %0, %1, %2;" : "=r"(r) : "f"(hi), "f"(lo));
    return r;
}
__device__ __forceinline__ void sts128(uint32_t a, uint32_t x, uint32_t y, uint32_t z, uint32_t w) {
    asm volatile("st.shared.v4.b32 [%0], {%1,%2,%3,%4};"
                 :: "r"(a), "r"(x), "r"(y), "r"(z), "r"(w) : "memory");
}
__device__ __forceinline__ void ldm4(uint32_t* r, uint32_t a) {
    asm volatile("ldmatrix.sync.aligned.m8n8.x4.shared.b16 {%0,%1,%2,%3}, [%4];"
                 : "=r"(r[0]), "=r"(r[1]), "=r"(r[2]), "=r"(r[3]) : "r"(a));
}
__device__ __forceinline__ void mma16816(float* d, const uint32_t* a, const uint32_t* b) {
    asm volatile("mma.sync.aligned.m16n8k16.row.col.f32.f16.f16.f32 "
                 "{%0,%1,%2,%3}, {%4,%5,%6,%7}, {%8,%9}, {%0,%1,%2,%3};"
                 : "+f"(d[0]), "+f"(d[1]), "+f"(d[2]), "+f"(d[3])
                 : "r"(a[0]), "r"(a[1]), "r"(a[2]), "r"(a[3]), "r"(b[0]), "r"(b[1]));
}
__device__ __forceinline__ void cp_async16(uint32_t dst, const void* src) {
    asm volatile("cp.async.cg.shared.global [%0], [%1], 16;" :: "r"(dst), "l"(src) : "memory");
}
#define CP_COMMIT asm volatile("cp.async.commit_group;" ::: "memory")
#define CP_WAIT0  asm volatile("cp.async.wait_group 0;" ::: "memory")

// ---------------- A convert kernel ----------------
__global__ void sct_cvtA(const float* __restrict__ A) {
    int i = blockIdx.x * 256 + threadIdx.x;   // 65536 elems
    g_A16[i] = __float2half_rn(A[i]);
}

// ---------------- main GEMM (persistent; clean hot loop + split tail) ------
__global__ __launch_bounds__(512, 1)
void sct_mma_kernel(const float* __restrict__ F, float* __restrict__ C,
                    int N, int ntiles)
{
    extern __shared__ char smem[];
    const uint32_t sb = smem_u32(smem);          // A resident: 8 chunks
    const uint32_t fb = sb + OFF_F;              // F stages (2)
    const int tid  = threadIdx.x;
    const int lane = tid & 31;
    const int wid  = tid >> 5;

    // ---- A residency load: once per CTA ----
    {
        const int ar = tid >> 1;                 // row 0..255
        const int ah = tid & 1;                  // 32B half
        const uint32_t dst0 = (uint32_t)ar * ROWB + (uint32_t)ah * 32u;
        const __half* src0 = g_A16 + ar * 256 + ah * 16;
        #pragma unroll
        for (int c = 0; c < NCH; c++) {
            const uint32_t dst = sb + (uint32_t)c * ACHUNK + dst0;
            const __half* src = src0 + c * KC;
            cp_async16(dst,      src);
            cp_async16(dst + 16, src + 8);
        }
        CP_COMMIT;
    }

    // F staging: row = tid>>2 (0..127), q = tid&3 -> 8 floats (32B)
    const int frow = tid >> 2;
    const int fq   = tid & 3;
    const uint32_t f_sts = (uint32_t)frow * ROWB + (uint32_t)fq * 16u;

    // warp tiling: 4 m-warps x 4 n-warps, warp tile 64x32
    const int wm = wid & 3;
    const int wn = wid >> 2;
    const int mbase = wm * 64;
    const int nb    = wn * 32;

    const uint32_t afrag = (uint32_t)(mbase + (lane & 15)) * ROWB + (uint32_t)((lane >> 4) * 16);
    const uint32_t bfrag = (uint32_t)(nb + (lane & 7) + ((lane >> 4) << 3)) * ROWB
                         + (uint32_t)(((lane >> 3) & 1) << 4);

    float4 pf0, pf1;
    const float* fsrc;
    auto fptr = [&](int tile) -> const float* {
        int fn = tile * NT + frow;
        if (fn > N - 1) fn = N - 1;              // clamp; stores guarded
        return F + (size_t)fn * 256 + fq * 8;
    };
    auto ldgF = [&](int c) {
        const float4* p = (const float4*)(fsrc + c * KC);
        pf0 = p[0]; pf1 = p[1];
    };
    auto stsF = [&](int c) {
        sts128(fb + (uint32_t)(c & 1) * FSTAGE + f_sts,
               pack_f16x2(pf0.y, pf0.x), pack_f16x2(pf0.w, pf0.z),
               pack_f16x2(pf1.y, pf1.x), pack_f16x2(pf1.w, pf1.z));
    };

    // wait for A once
    CP_WAIT0;

    const int stride = gridDim.x;
    const int full   = ntiles / stride;
    const int rem    = ntiles - full * stride;
    const bool split = (2 * rem <= stride);

    // my tail assignment
    int tail = -1, mhalf = 0;
    if (rem > 0) {
        if (split) {
            if ((int)blockIdx.x < 2 * rem) {
                tail  = full * stride + ((int)blockIdx.x >> 1);
                mhalf = blockIdx.x & 1;
            }
        } else if ((int)blockIdx.x < rem) {
            tail = full * stride + blockIdx.x;
        }
    }

    // =============== full rounds: EXACT R12 hot loop, no gating ===========
    if (full > 0) {
        fsrc = fptr(blockIdx.x);
        ldgF(0);
        #pragma unroll 1
        for (int r = 0; r < full; r++) {
            const int tile = blockIdx.x + r * stride;
            const int n0 = tile * NT;

            float acc[4][4][4];
            #pragma unroll
            for (int i = 0; i < 4; i++)
                #pragma unroll
                for (int j = 0; j < 4; j++)
                    #pragma unroll
                    for (int q = 0; q < 4; q++) acc[i][j][q] = 0.0f;

            stsF(0);
            __syncthreads();

            #pragma unroll
            for (int c = 0; c < NCH; c++) {
                if (c + 1 < NCH) ldgF(c + 1);
                {
                    const uint32_t ast = sb + (uint32_t)c * ACHUNK;
                    const uint32_t fst = fb + (uint32_t)(c & 1) * FSTAGE;
                    #pragma unroll
                    for (int ks = 0; ks < 2; ks++) {
                        const uint32_t ko = ks * 32;
                        uint32_t b0[4], b1[4], a[4][4];
                        ldm4(b0, fst + bfrag + ko);                 // n-tiles 0,1
                        ldm4(b1, fst + bfrag + 16 * ROWB + ko);     // n-tiles 2,3
                        #pragma unroll
                        for (int i = 0; i < 4; i++)
                            ldm4(a[i], ast + afrag + (uint32_t)i * (16 * ROWB) + ko);
                        #pragma unroll
                        for (int i = 0; i < 4; i++) {
                            mma16816(acc[i][0], a[i], b0 + 0);
                            mma16816(acc[i][1], a[i], b0 + 2);
                            mma16816(acc[i][2], a[i], b1 + 0);
                            mma16816(acc[i][3], a[i], b1 + 2);
                        }
                    }
                }
                if (c + 1 < NCH) {
                    stsF(c + 1);
                    __syncthreads();
                }
            }

            // prefetch next tile's F chunk 0 so the epilogue stores hide it
            if (r + 1 < full)      { fsrc = fptr(tile + stride); ldgF(0); }
            else if (tail >= 0)    { fsrc = fptr(tail);          ldgF(0); }

            #pragma unroll
            for (int i = 0; i < 4; i++) {
                const int m = mbase + i * 16 + (lane >> 2);
                #pragma unroll
                for (int j = 0; j < 4; j++) {
                    const int n = n0 + nb + j * 8 + (lane & 3) * 2;
                    if (n < N) {   // N even, n even -> n+1 also valid
                        float* p0 = C + (size_t)m * N + n;
                        float* p1 = C + (size_t)(m + 8) * N + n;
                        *(float2*)p0 = make_float2(acc[i][j][0] * SCALE, acc[i][j][1] * SCALE);
                        *(float2*)p1 = make_float2(acc[i][j][2] * SCALE, acc[i][j][3] * SCALE);
                    }
                }
            }
        }
    }

    // =============== tail: separate duplicated path, per-warp gated =======
    if (tail >= 0) {
        if (full == 0) { fsrc = fptr(tail); ldgF(0); }
        const bool act = split ? ((wm >> 1) == mhalf) : true;
        const int n0 = tail * NT;

        float acc[4][4][4];
        #pragma unroll
        for (int i = 0; i < 4; i++)
            #pragma unroll
            for (int j = 0; j < 4; j++)
                #pragma unroll
                for (int q = 0; q < 4; q++) acc[i][j][q] = 0.0f;

        stsF(0);
        __syncthreads();

        #pragma unroll
        for (int c = 0; c < NCH; c++) {
            if (c + 1 < NCH) ldgF(c + 1);
            if (act) {
                const uint32_t ast = sb + (uint32_t)c * ACHUNK;
                const uint32_t fst = fb + (uint32_t)(c & 1) * FSTAGE;
                #pragma unroll
                for (int ks = 0; ks < 2; ks++) {
                    const uint32_t ko = ks * 32;
                    uint32_t b0[4], b1[4], a[4][4];
                    ldm4(b0, fst + bfrag + ko);
                    ldm4(b1, fst + bfrag + 16 * ROWB + ko);
                    #pragma unroll
                    for (int i = 0; i < 4; i++)
                        ldm4(a[i], ast + afrag + (uint32_t)i * (16 * ROWB) + ko);
                    #pragma unroll
                    for (int i = 0; i < 4; i++) {
                        mma16816(acc[i][0], a[i], b0 + 0);
                        mma16816(acc[i][1], a[i], b0 + 2);
                        mma16816(acc[i][2], a[i], b1 + 0);
                        mma16816(acc[i][3], a[i], b1 + 2);
                    }
                }
            }
            if (c + 1 < NCH) {
                stsF(c + 1);
                __syncthreads();
            }
        }

        if (act) {
            #pragma unroll
            for (int i = 0; i < 4; i++) {
                const int m = mbase + i * 16 + (lane >> 2);
                #pragma unroll
                for (int j = 0; j < 4; j++) {
                    const int n = n0 + nb + j * 8 + (lane & 3) * 2;
                    if (n < N) {
                        float* p0 = C + (size_t)m * N + n;
                        float* p1 = C + (size_t)(m + 8) * N + n;
                        *(float2*)p0 = make_float2(acc[i][j][0] * SCALE, acc[i][j][1] * SCALE);
                        *(float2*)p1 = make_float2(acc[i][j][2] * SCALE, acc[i][j][3] * SCALE);
                    }
                }
            }
        }
    }
}

// ---------------- launch ----------------
extern "C" void kernel_launch(void* const* d_in, const int* in_sizes, int n_in,
                              void* d_out, int out_size)
{
    const float* inputs   = (const float*)d_in[0];  // [256, 256]
    const float* features = (const float*)d_in[2];  // [N, 256]
    const int D = 256;
    const int N = in_sizes[2] / D;

    sct_cvtA<<<256, 256>>>(inputs);

    int nsm = 148;
    cudaDeviceGetAttribute(&nsm, cudaDevAttrMultiProcessorCount, 0);

    const int ntiles = (N + NT - 1) / NT;
    int grid = nsm < ntiles ? nsm : ntiles;

    cudaFuncSetAttribute(sct_mma_kernel, cudaFuncAttributeMaxDynamicSharedMemorySize, SMEM_TOTAL);
    sct_mma_kernel<<<grid, 512, SMEM_TOTAL>>>(features, (float*)d_out, N, ntiles);
}